// round 2
// baseline (speedup 1.0000x reference)
#include <cuda_runtime.h>
#include <cuda_bf16.h>
#include <math.h>

// ---------------- problem constants ----------------
#define EMB 128
#define HID 256
#define EDIM 16
#define NGRAPH 512
#define NLAYER 3
#define MAXN 100352          // capacity >= 100000, multiple of 64
#define MAXE 600064

// ---------------- scratch (device globals; no runtime alloc) ----------------
__device__ float g_hin[(size_t)MAXN * EMB];
__device__ float g_agg[(size_t)MAXN * EMB];
__device__ float g_h  [(size_t)MAXN * EMB];
__device__ float g_vn [NGRAPH * EMB];
__device__ float g_vt [NGRAPH * EMB];

// ---------------- helpers ----------------
__device__ __forceinline__ void red_add_v4(float* p, float4 v) {
    asm volatile("red.global.add.v4.f32 [%0], {%1,%2,%3,%4};"
                 :: "l"(p), "f"(v.x), "f"(v.y), "f"(v.z), "f"(v.w) : "memory");
}

// ---------------- kernel 0: init vn = broadcast(vn_emb) ----------------
__global__ void k_init_vn(const float* __restrict__ vn_emb, float* __restrict__ vn) {
    int i = blockIdx.x * blockDim.x + threadIdx.x;
    if (i < NGRAPH * EMB) vn[i] = vn_emb[i & (EMB - 1)];
}

// ---------------- kernel 1: hin = h + vn[batch]; vt += segment_sum(hin) ----------------
// block: 32 x 8 threads, 64 nodes/block. batch is SORTED -> run-length flush.
__global__ void k_hin_vt(const float* __restrict__ h, const int* __restrict__ batch,
                         const float* __restrict__ vn, float* __restrict__ hin,
                         float* __restrict__ vt, int N, int doVT) {
    int lane = threadIdx.x;          // 0..31  -> feature float4
    int row  = threadIdx.y;          // 0..7
    int base = blockIdx.x * 64;
    float4 acc = make_float4(0.f, 0.f, 0.f, 0.f);
    int gcur = -1;
    for (int it = 0; it < 8; it++) {
        int i = base + it * 8 + row;
        if (i >= N) break;
        int g = batch[i];
        const float4 hv = *(const float4*)&h[(size_t)i * EMB + lane * 4];
        const float4 vv = *(const float4*)&vn[(size_t)g * EMB + lane * 4];
        float4 s = make_float4(hv.x + vv.x, hv.y + vv.y, hv.z + vv.z, hv.w + vv.w);
        *(float4*)&hin[(size_t)i * EMB + lane * 4] = s;
        if (doVT) {
            if (g != gcur) {
                if (gcur >= 0) red_add_v4(&vt[(size_t)gcur * EMB + lane * 4], acc);
                acc = make_float4(0.f, 0.f, 0.f, 0.f);
                gcur = g;
            }
            acc.x += s.x; acc.y += s.y; acc.z += s.z; acc.w += s.w;
        }
    }
    if (doVT && gcur >= 0) red_add_v4(&vt[(size_t)gcur * EMB + lane * 4], acc);
}

// ---------------- kernel 2: edge conv ----------------
// per edge: emb = edge_attr @ We + be; msg = relu(hin[src] + emb); agg[dst] += msg
// block: 256 threads = 8 warps, 4 edges/warp -> 32 edges/block. We (16x128) staged in smem.
__global__ __launch_bounds__(256) void k_edge(const float* __restrict__ hin,
                                              const float* __restrict__ ea,
                                              const int* __restrict__ eidx,
                                              const float* __restrict__ We,
                                              const float* __restrict__ be,
                                              float* __restrict__ agg, int E) {
    __shared__ float sW[EDIM * EMB];
    __shared__ float sb[EMB];
    int tid = threadIdx.x;
#pragma unroll
    for (int t = 0; t < 8; t++) sW[tid + 256 * t] = We[tid + 256 * t];
    if (tid < EMB) sb[tid] = be[tid];
    __syncthreads();

    int warp = tid >> 5, lane = tid & 31;
    long long ebase = (long long)blockIdx.x * 32 + warp * 4;
#pragma unroll
    for (int ew = 0; ew < 4; ew++) {
        long long e = ebase + ew;
        if (e >= E) break;
        float eav = (lane < EDIM) ? ea[e * EDIM + lane] : 0.f;
        int src = eidx[e];
        int dst = eidx[E + e];
        float4 emb = *(const float4*)&sb[lane * 4];
#pragma unroll
        for (int k = 0; k < EDIM; k++) {
            float ek = __shfl_sync(0xffffffffu, eav, k);
            float4 w = *(const float4*)&sW[k * EMB + lane * 4];
            emb.x += ek * w.x; emb.y += ek * w.y; emb.z += ek * w.z; emb.w += ek * w.w;
        }
        float4 x = *(const float4*)&hin[(size_t)src * EMB + lane * 4];
        float4 m = make_float4(fmaxf(x.x + emb.x, 0.f), fmaxf(x.y + emb.y, 0.f),
                               fmaxf(x.z + emb.z, 0.f), fmaxf(x.w + emb.w, 0.f));
        red_add_v4(&agg[(size_t)dst * EMB + lane * 4], m);
    }
}

// ---------------- kernel 3: fused node MLP + BN + relu + residual ----------------
// x = hin + agg;  hid = relu(x@W1 + b1);  z = hid@W2 + b2; z = z*(g*inv)+b; [relu]; z += hin
// block = 256 threads, 64 nodes. Tiled fp32 GEMM, weights staged in smem in k-chunks.
#define XS_STRIDE 132
#define HS_STRIDE 260
#define MLP_SMEM_FLOATS (64 * XS_STRIDE + 64 * HS_STRIDE + 32 * 256)

__global__ __launch_bounds__(256, 1) void k_node_mlp(
    const float* __restrict__ hin, const float* __restrict__ agg,
    const float* __restrict__ W1, const float* __restrict__ b1,
    const float* __restrict__ W2, const float* __restrict__ b2,
    const float* __restrict__ gamma, const float* __restrict__ beta,
    float* __restrict__ out, int N, int relu_out, float inv) {
    extern __shared__ float smf[];
    float* Xs = smf;
    float* Hs = smf + 64 * XS_STRIDE;
    float* Ws = Hs + 64 * HS_STRIDE;

    int tid = threadIdx.x;
    int base = blockIdx.x * 64;
    int rg = tid >> 4;    // 16 row-groups * 4 rows
    int cg = tid & 15;    // 16 col-groups

    // load X = hin + agg (64 x 128)
#pragma unroll
    for (int t = 0; t < 8; t++) {
        int li = tid + t * 256;
        int row = li >> 5;
        int c4 = (li & 31) * 4;
        int node = base + row;
        float4 v = make_float4(0.f, 0.f, 0.f, 0.f);
        if (node < N) {
            float4 a = *(const float4*)&hin[(size_t)node * EMB + c4];
            float4 b = *(const float4*)&agg[(size_t)node * EMB + c4];
            v = make_float4(a.x + b.x, a.y + b.y, a.z + b.z, a.w + b.w);
        }
        *(float4*)&Xs[row * XS_STRIDE + c4] = v;
    }

    // ---- GEMM1: C1[64x256] = X[64x128] @ W1[128x256] ----
    float acc[4][16];
#pragma unroll
    for (int r = 0; r < 4; r++)
#pragma unroll
        for (int c = 0; c < 16; c++) acc[r][c] = 0.f;

    for (int kc = 0; kc < 4; kc++) {
        __syncthreads();
#pragma unroll
        for (int t = 0; t < 8; t++) {
            int li = tid + t * 256;
            int kk = li >> 6;
            int c4 = (li & 63) * 4;
            *(float4*)&Ws[kk * 256 + c4] = *(const float4*)&W1[(size_t)(kc * 32 + kk) * 256 + c4];
        }
        __syncthreads();
#pragma unroll
        for (int k = 0; k < 32; k++) {
            int kf = kc * 32 + k;
            float a0 = Xs[(rg * 4 + 0) * XS_STRIDE + kf];
            float a1 = Xs[(rg * 4 + 1) * XS_STRIDE + kf];
            float a2 = Xs[(rg * 4 + 2) * XS_STRIDE + kf];
            float a3 = Xs[(rg * 4 + 3) * XS_STRIDE + kf];
            const float* wr = &Ws[k * 256 + cg * 16];
            float4 b0 = *(const float4*)&wr[0];
            float4 b1v = *(const float4*)&wr[4];
            float4 b2v = *(const float4*)&wr[8];
            float4 b3v = *(const float4*)&wr[12];
            float bb[16] = {b0.x, b0.y, b0.z, b0.w, b1v.x, b1v.y, b1v.z, b1v.w,
                            b2v.x, b2v.y, b2v.z, b2v.w, b3v.x, b3v.y, b3v.z, b3v.w};
#pragma unroll
            for (int c = 0; c < 16; c++) {
                acc[0][c] += a0 * bb[c];
                acc[1][c] += a1 * bb[c];
                acc[2][c] += a2 * bb[c];
                acc[3][c] += a3 * bb[c];
            }
        }
    }

    // bias + relu -> Hs
    {
        float4 bA = *(const float4*)&b1[cg * 16 + 0];
        float4 bB = *(const float4*)&b1[cg * 16 + 4];
        float4 bC = *(const float4*)&b1[cg * 16 + 8];
        float4 bD = *(const float4*)&b1[cg * 16 + 12];
        float bb1[16] = {bA.x, bA.y, bA.z, bA.w, bB.x, bB.y, bB.z, bB.w,
                         bC.x, bC.y, bC.z, bC.w, bD.x, bD.y, bD.z, bD.w};
#pragma unroll
        for (int r = 0; r < 4; r++) {
            int row = rg * 4 + r;
#pragma unroll
            for (int c = 0; c < 16; c++)
                Hs[row * HS_STRIDE + cg * 16 + c] = fmaxf(acc[r][c] + bb1[c], 0.f);
        }
    }

    // ---- GEMM2: Z[64x128] = H[64x256] @ W2[256x128] ----
    float acc2[4][8];
#pragma unroll
    for (int r = 0; r < 4; r++)
#pragma unroll
        for (int c = 0; c < 8; c++) acc2[r][c] = 0.f;

    for (int kc = 0; kc < 8; kc++) {
        __syncthreads();
#pragma unroll
        for (int t = 0; t < 4; t++) {
            int li = tid + t * 256;
            int kk = li >> 5;
            int c4 = (li & 31) * 4;
            *(float4*)&Ws[kk * 128 + c4] = *(const float4*)&W2[(size_t)(kc * 32 + kk) * 128 + c4];
        }
        __syncthreads();
#pragma unroll
        for (int j = 0; j < 32; j++) {
            int jf = kc * 32 + j;
            float a0 = Hs[(rg * 4 + 0) * HS_STRIDE + jf];
            float a1 = Hs[(rg * 4 + 1) * HS_STRIDE + jf];
            float a2 = Hs[(rg * 4 + 2) * HS_STRIDE + jf];
            float a3 = Hs[(rg * 4 + 3) * HS_STRIDE + jf];
            float4 c0 = *(const float4*)&Ws[j * 128 + cg * 8];
            float4 c1 = *(const float4*)&Ws[j * 128 + cg * 8 + 4];
            float cc[8] = {c0.x, c0.y, c0.z, c0.w, c1.x, c1.y, c1.z, c1.w};
#pragma unroll
            for (int c = 0; c < 8; c++) {
                acc2[0][c] += a0 * cc[c];
                acc2[1][c] += a1 * cc[c];
                acc2[2][c] += a2 * cc[c];
                acc2[3][c] += a3 * cc[c];
            }
        }
    }

    // epilogue: bias, BN, optional relu, residual
    {
        int cb = cg * 8;
        float4 b2a = *(const float4*)&b2[cb];
        float4 b2b = *(const float4*)&b2[cb + 4];
        float4 ga  = *(const float4*)&gamma[cb];
        float4 gb  = *(const float4*)&gamma[cb + 4];
        float4 ba  = *(const float4*)&beta[cb];
        float4 bb_ = *(const float4*)&beta[cb + 4];
        float bv[8]  = {b2a.x, b2a.y, b2a.z, b2a.w, b2b.x, b2b.y, b2b.z, b2b.w};
        float gv[8]  = {ga.x * inv, ga.y * inv, ga.z * inv, ga.w * inv,
                        gb.x * inv, gb.y * inv, gb.z * inv, gb.w * inv};
        float bev[8] = {ba.x, ba.y, ba.z, ba.w, bb_.x, bb_.y, bb_.z, bb_.w};
#pragma unroll
        for (int r = 0; r < 4; r++) {
            int node = base + rg * 4 + r;
            if (node >= N) continue;
            float4 h0 = *(const float4*)&hin[(size_t)node * EMB + cb];
            float4 h1 = *(const float4*)&hin[(size_t)node * EMB + cb + 4];
            float hres[8] = {h0.x, h0.y, h0.z, h0.w, h1.x, h1.y, h1.z, h1.w};
            float zr[8];
#pragma unroll
            for (int c = 0; c < 8; c++) {
                float z = acc2[r][c] + bv[c];
                z = z * gv[c] + bev[c];
                if (relu_out) z = fmaxf(z, 0.f);
                zr[c] = z + hres[c];
            }
            *(float4*)&out[(size_t)node * EMB + cb]     = make_float4(zr[0], zr[1], zr[2], zr[3]);
            *(float4*)&out[(size_t)node * EMB + cb + 4] = make_float4(zr[4], zr[5], zr[6], zr[7]);
        }
    }
}

// ---------------- kernel 4: virtual-node MLP (512 graphs) ----------------
__global__ __launch_bounds__(256) void k_vn_mlp(
    const float* __restrict__ vt, float* __restrict__ vn,
    const float* __restrict__ w1, const float* __restrict__ b1,
    const float* __restrict__ g1, const float* __restrict__ be1,
    const float* __restrict__ w2, const float* __restrict__ b2,
    const float* __restrict__ g2, const float* __restrict__ be2, float inv) {
    __shared__ float sv[EMB];
    __shared__ float sm1[HID];
    int g = blockIdx.x;
    int tid = threadIdx.x;
    if (tid < EMB) sv[tid] = vt[(size_t)g * EMB + tid] + vn[(size_t)g * EMB + tid];
    __syncthreads();
    {
        int j = tid;
        float s = b1[j];
#pragma unroll 8
        for (int k = 0; k < EMB; k++) s += sv[k] * w1[(size_t)k * HID + j];
        s = s * (g1[j] * inv) + be1[j];
        sm1[j] = fmaxf(s, 0.f);
    }
    __syncthreads();
    if (tid < EMB) {
        int c = tid;
        float s = b2[c];
#pragma unroll 8
        for (int j = 0; j < HID; j++) s += sm1[j] * w2[(size_t)j * EMB + c];
        s = s * (g2[c] * inv) + be2[c];
        vn[(size_t)g * EMB + c] += fmaxf(s, 0.f);
    }
}

// ---------------- host orchestration ----------------
extern "C" void kernel_launch(void* const* d_in, const int* in_sizes, int n_in,
                              void* d_out, int out_size) {
    if (n_in < 21) return;

    const float* input_feature = (const float*)d_in[0];
    // inputs 1/2 are edge_index (int32, 2E) and edge_attr (f32, 16E) in some order:
    const int* edge_index;
    const float* edge_attr;
    long long E;
    if ((long long)in_sizes[1] < (long long)in_sizes[2]) {
        edge_index = (const int*)d_in[1];
        edge_attr  = (const float*)d_in[2];
        E = in_sizes[1] / 2;
    } else {
        edge_index = (const int*)d_in[2];
        edge_attr  = (const float*)d_in[1];
        E = in_sizes[2] / 2;
    }
    const int* batch = (const int*)d_in[3];
    int N = in_sizes[0] / EMB;

    const float* vn_emb = (const float*)d_in[4];
    const float* cew = (const float*)d_in[5];   // [3,16,128]
    const float* ceb = (const float*)d_in[6];   // [3,128]
    const float* cw1 = (const float*)d_in[7];   // [3,128,256]
    const float* cb1 = (const float*)d_in[8];   // [3,256]
    const float* cw2 = (const float*)d_in[9];   // [3,256,128]
    const float* cb2 = (const float*)d_in[10];  // [3,128]
    const float* bng = (const float*)d_in[11];  // [3,128]
    const float* bnb = (const float*)d_in[12];  // [3,128]
    const float* vw1 = (const float*)d_in[13];  // [2,128,256]
    const float* vb1 = (const float*)d_in[14];  // [2,256]
    const float* vg1 = (const float*)d_in[15];  // [2,256]
    const float* vbe1 = (const float*)d_in[16]; // [2,256]
    const float* vw2 = (const float*)d_in[17];  // [2,256,128]
    const float* vb2 = (const float*)d_in[18];  // [2,128]
    const float* vg2 = (const float*)d_in[19];  // [2,128]
    const float* vbe2 = (const float*)d_in[20]; // [2,128]

    float* hin; float* agg; float* hbuf; float* vn; float* vt;
    cudaGetSymbolAddress((void**)&hin, g_hin);
    cudaGetSymbolAddress((void**)&agg, g_agg);
    cudaGetSymbolAddress((void**)&hbuf, g_h);
    cudaGetSymbolAddress((void**)&vn, g_vn);
    cudaGetSymbolAddress((void**)&vt, g_vt);

    cudaFuncSetAttribute(k_node_mlp, cudaFuncAttributeMaxDynamicSharedMemorySize,
                         MLP_SMEM_FLOATS * (int)sizeof(float));

    const float inv = 1.0f / sqrtf(1.0f + 1e-5f);

    // vn <- broadcast(vn_emb)
    k_init_vn<<<(NGRAPH * EMB + 255) / 256, 256>>>(vn_emb, vn);

    int nblk = (N + 63) / 64;
    int eblk = (int)((E + 31) / 32);

    const float* h = input_feature;
    for (int l = 0; l < NLAYER; l++) {
        int doVT = (l < NLAYER - 1);
        cudaMemsetAsync(agg, 0, (size_t)N * EMB * sizeof(float));
        if (doVT) cudaMemsetAsync(vt, 0, (size_t)NGRAPH * EMB * sizeof(float));

        k_hin_vt<<<nblk, dim3(32, 8)>>>(h, batch, vn, hin, vt, N, doVT);

        k_edge<<<eblk, 256>>>(hin, edge_attr, edge_index,
                              cew + (size_t)l * EDIM * EMB, ceb + (size_t)l * EMB,
                              agg, (int)E);

        float* outp = (l == NLAYER - 1) ? (float*)d_out : hbuf;
        k_node_mlp<<<nblk, 256, MLP_SMEM_FLOATS * (int)sizeof(float)>>>(
            hin, agg,
            cw1 + (size_t)l * EMB * HID, cb1 + (size_t)l * HID,
            cw2 + (size_t)l * HID * EMB, cb2 + (size_t)l * EMB,
            bng + (size_t)l * EMB, bnb + (size_t)l * EMB,
            outp, N, doVT ? 1 : 0, inv);

        if (doVT) {
            k_vn_mlp<<<NGRAPH, 256>>>(vt, vn,
                                      vw1 + (size_t)l * EMB * HID, vb1 + (size_t)l * HID,
                                      vg1 + (size_t)l * HID, vbe1 + (size_t)l * HID,
                                      vw2 + (size_t)l * HID * EMB, vb2 + (size_t)l * EMB,
                                      vg2 + (size_t)l * EMB, vbe2 + (size_t)l * EMB, inv);
        }
        h = outp;
    }
}

// round 3
// speedup vs baseline: 2.0338x; 2.0338x over previous
#include <cuda_runtime.h>
#include <cuda_bf16.h>
#include <math.h>

// ---------------- problem constants ----------------
#define EMB 128
#define HID 256
#define EDIM 16
#define NGRAPH 512
#define NLAYER 3
#define MAXN 100352
#define MAXE 600064

// ---------------- scratch (device globals) ----------------
__device__ float g_hin[(size_t)MAXN * EMB];
__device__ float g_agg[(size_t)MAXN * EMB];
__device__ float g_h  [(size_t)MAXN * EMB];
__device__ float g_vn [NGRAPH * EMB];
__device__ float g_vt [NGRAPH * EMB];

// ---------------- helpers ----------------
__device__ __forceinline__ void red_add_v4(float* p, float4 v) {
    asm volatile("red.global.add.v4.f32 [%0], {%1,%2,%3,%4};"
                 :: "l"(p), "f"(v.x), "f"(v.y), "f"(v.z), "f"(v.w) : "memory");
}
__device__ __forceinline__ unsigned f2tf(float f) {
    unsigned r; asm("cvt.rna.tf32.f32 %0, %1;" : "=r"(r) : "f"(f)); return r;
}
__device__ __forceinline__ void mma_tf32(float* c, const unsigned* a, unsigned b0, unsigned b1) {
    asm volatile("mma.sync.aligned.m16n8k8.row.col.f32.tf32.tf32.f32 "
                 "{%0,%1,%2,%3},{%4,%5,%6,%7},{%8,%9},{%0,%1,%2,%3};"
                 : "+f"(c[0]), "+f"(c[1]), "+f"(c[2]), "+f"(c[3])
                 : "r"(a[0]), "r"(a[1]), "r"(a[2]), "r"(a[3]), "r"(b0), "r"(b1));
}

// ---------------- kernel 0: init vn ----------------
__global__ void k_init_vn(const float* __restrict__ vn_emb, float* __restrict__ vn) {
    int i = blockIdx.x * blockDim.x + threadIdx.x;
    if (i < NGRAPH * EMB) vn[i] = vn_emb[i & (EMB - 1)];
}

// ---------------- kernel 1: hin = h + vn[batch]; vt += segsum(hin) ----------------
__global__ void k_hin_vt(const float* __restrict__ h, const int* __restrict__ batch,
                         const float* __restrict__ vn, float* __restrict__ hin,
                         float* __restrict__ vt, int N, int doVT) {
    int lane = threadIdx.x;
    int row  = threadIdx.y;
    int base = blockIdx.x * 64;
    float4 acc = make_float4(0.f, 0.f, 0.f, 0.f);
    int gcur = -1;
    for (int it = 0; it < 8; it++) {
        int i = base + it * 8 + row;
        if (i >= N) break;
        int g = batch[i];
        const float4 hv = *(const float4*)&h[(size_t)i * EMB + lane * 4];
        const float4 vv = *(const float4*)&vn[(size_t)g * EMB + lane * 4];
        float4 s = make_float4(hv.x + vv.x, hv.y + vv.y, hv.z + vv.z, hv.w + vv.w);
        *(float4*)&hin[(size_t)i * EMB + lane * 4] = s;
        if (doVT) {
            if (g != gcur) {
                if (gcur >= 0) red_add_v4(&vt[(size_t)gcur * EMB + lane * 4], acc);
                acc = make_float4(0.f, 0.f, 0.f, 0.f);
                gcur = g;
            }
            acc.x += s.x; acc.y += s.y; acc.z += s.z; acc.w += s.w;
        }
    }
    if (doVT && gcur >= 0) red_add_v4(&vt[(size_t)gcur * EMB + lane * 4], acc);
}

// ---------------- kernel 2: edge conv ----------------
__global__ __launch_bounds__(256) void k_edge(const float* __restrict__ hin,
                                              const float* __restrict__ ea,
                                              const int* __restrict__ eidx,
                                              const float* __restrict__ We,
                                              const float* __restrict__ be,
                                              float* __restrict__ agg, int E) {
    __shared__ float sW[EDIM * EMB];
    __shared__ float sb[EMB];
    int tid = threadIdx.x;
#pragma unroll
    for (int t = 0; t < 8; t++) sW[tid + 256 * t] = We[tid + 256 * t];
    if (tid < EMB) sb[tid] = be[tid];
    __syncthreads();

    int warp = tid >> 5, lane = tid & 31;
    long long ebase = (long long)blockIdx.x * 32 + warp * 4;
#pragma unroll
    for (int ew = 0; ew < 4; ew++) {
        long long e = ebase + ew;
        if (e >= E) break;
        float eav = (lane < EDIM) ? ea[e * EDIM + lane] : 0.f;
        int src = eidx[e];
        int dst = eidx[E + e];
        float4 emb = *(const float4*)&sb[lane * 4];
#pragma unroll
        for (int k = 0; k < EDIM; k++) {
            float ek = __shfl_sync(0xffffffffu, eav, k);
            float4 w = *(const float4*)&sW[k * EMB + lane * 4];
            emb.x += ek * w.x; emb.y += ek * w.y; emb.z += ek * w.z; emb.w += ek * w.w;
        }
        float4 x = *(const float4*)&hin[(size_t)src * EMB + lane * 4];
        float4 m = make_float4(fmaxf(x.x + emb.x, 0.f), fmaxf(x.y + emb.y, 0.f),
                               fmaxf(x.z + emb.z, 0.f), fmaxf(x.w + emb.w, 0.f));
        red_add_v4(&agg[(size_t)dst * EMB + lane * 4], m);
    }
}

// ---------------- kernel 3: tensor-core node MLP (tf32 mma) ----------------
// 64 nodes per CTA, 256 threads = 8 warps.
// GEMM1: [64x128]@[128x256] warp grid 2x4, warp tile 32x64 (2 m-tiles x 8 n-tiles)
// GEMM2: [64x256]@[256x128] warp grid 2x4, warp tile 32x32 (2 m-tiles x 4 n-tiles)
#define XS_STR 132   // A operand: bank (4g+t) conflict-free
#define HS_STR 260   // A operand: bank (4g+t) conflict-free
#define W1_STR 264   // B operand: bank (8k+n) conflict-free
#define W2_STR 136   // B operand: bank (8k+n) conflict-free
#define MLP_SMEM_FLOATS (64 * XS_STR + 64 * HS_STR + 16 * W1_STR)

__global__ __launch_bounds__(256, 1) void k_node_mlp(
    const float* __restrict__ hin, const float* __restrict__ agg,
    const float* __restrict__ W1, const float* __restrict__ b1,
    const float* __restrict__ W2, const float* __restrict__ b2,
    const float* __restrict__ gamma, const float* __restrict__ beta,
    float* __restrict__ out, int N, int relu_out, float inv) {
    extern __shared__ float smf[];
    float* Xs = smf;                    // 64 x XS_STR
    float* Hs = smf + 64 * XS_STR;      // 64 x HS_STR
    float* Ws = Hs + 64 * HS_STR;       // 16 x W1_STR (reused: 16 x W2_STR)

    int tid = threadIdx.x;
    int wid = tid >> 5, lane = tid & 31;
    int g = lane >> 2, t = lane & 3;
    int warp_m = wid >> 2;   // 0..1
    int warp_n = wid & 3;    // 0..3
    int base = blockIdx.x * 64;

    // ---- stage X = tf32(hin + agg), 64 x 128 ----
#pragma unroll
    for (int p = 0; p < 8; p++) {
        int li = tid + p * 256;
        int row = li >> 5;
        int c4 = (li & 31) * 4;
        int node = base + row;
        float4 v = make_float4(0.f, 0.f, 0.f, 0.f);
        if (node < N) {
            float4 a = *(const float4*)&hin[(size_t)node * EMB + c4];
            float4 b = *(const float4*)&agg[(size_t)node * EMB + c4];
            v = make_float4(a.x + b.x, a.y + b.y, a.z + b.z, a.w + b.w);
        }
        float* d = &Xs[row * XS_STR + c4];
        d[0] = __uint_as_float(f2tf(v.x));
        d[1] = __uint_as_float(f2tf(v.y));
        d[2] = __uint_as_float(f2tf(v.z));
        d[3] = __uint_as_float(f2tf(v.w));
    }

    // ---- GEMM1 with register-prefetched W1 chunks (KC=16, 8 chunks) ----
    float c1[2][8][4];
#pragma unroll
    for (int mt = 0; mt < 2; mt++)
#pragma unroll
        for (int nt = 0; nt < 8; nt++)
#pragma unroll
            for (int j = 0; j < 4; j++) c1[mt][nt][j] = 0.f;

    float4 wreg[4];
    // prefetch chunk 0: 16 rows x 256 cols = 1024 float4
#pragma unroll
    for (int p = 0; p < 4; p++) {
        int idx4 = tid + p * 256;
        int row = idx4 >> 6, col4 = idx4 & 63;
        wreg[p] = *(const float4*)&W1[(size_t)row * 256 + col4 * 4];
    }
#pragma unroll
    for (int p = 0; p < 4; p++) {
        int idx4 = tid + p * 256;
        int row = idx4 >> 6, col4 = idx4 & 63;
        float* d = &Ws[row * W1_STR + col4 * 4];
        d[0] = __uint_as_float(f2tf(wreg[p].x));
        d[1] = __uint_as_float(f2tf(wreg[p].y));
        d[2] = __uint_as_float(f2tf(wreg[p].z));
        d[3] = __uint_as_float(f2tf(wreg[p].w));
    }
    __syncthreads();

    for (int kc = 0; kc < 8; kc++) {
        if (kc < 7) {
#pragma unroll
            for (int p = 0; p < 4; p++) {
                int idx4 = tid + p * 256;
                int row = idx4 >> 6, col4 = idx4 & 63;
                wreg[p] = *(const float4*)&W1[(size_t)((kc + 1) * 16 + row) * 256 + col4 * 4];
            }
        }
        // compute this chunk: 2 k-steps of 8
#pragma unroll
        for (int ks = 0; ks < 2; ks++) {
            int kl = ks * 8;
            int kg = kc * 16 + kl;
            unsigned a[2][4];
#pragma unroll
            for (int mt = 0; mt < 2; mt++) {
                int r = warp_m * 32 + mt * 16 + g;
                const float* x0 = &Xs[r * XS_STR + kg + t];
                const float* x8 = &Xs[(r + 8) * XS_STR + kg + t];
                a[mt][0] = __float_as_uint(x0[0]);
                a[mt][1] = __float_as_uint(x8[0]);
                a[mt][2] = __float_as_uint(x0[4]);
                a[mt][3] = __float_as_uint(x8[4]);
            }
#pragma unroll
            for (int nt = 0; nt < 8; nt++) {
                int col = warp_n * 64 + nt * 8 + g;
                unsigned b0 = __float_as_uint(Ws[(kl + t) * W1_STR + col]);
                unsigned b1r = __float_as_uint(Ws[(kl + t + 4) * W1_STR + col]);
                mma_tf32(c1[0][nt], a[0], b0, b1r);
                mma_tf32(c1[1][nt], a[1], b0, b1r);
            }
        }
        __syncthreads();
        if (kc < 7) {
#pragma unroll
            for (int p = 0; p < 4; p++) {
                int idx4 = tid + p * 256;
                int row = idx4 >> 6, col4 = idx4 & 63;
                float* d = &Ws[row * W1_STR + col4 * 4];
                d[0] = __uint_as_float(f2tf(wreg[p].x));
                d[1] = __uint_as_float(f2tf(wreg[p].y));
                d[2] = __uint_as_float(f2tf(wreg[p].z));
                d[3] = __uint_as_float(f2tf(wreg[p].w));
            }
            __syncthreads();
        }
    }

    // ---- epilogue1: bias + relu -> Hs (tf32) ----
#pragma unroll
    for (int nt = 0; nt < 8; nt++) {
        int c0 = warp_n * 64 + nt * 8 + t * 2;
        float bb0 = __ldg(&b1[c0]);
        float bb1 = __ldg(&b1[c0 + 1]);
#pragma unroll
        for (int mt = 0; mt < 2; mt++) {
            int r = warp_m * 32 + mt * 16 + g;
            Hs[r * HS_STR + c0]           = __uint_as_float(f2tf(fmaxf(c1[mt][nt][0] + bb0, 0.f)));
            Hs[r * HS_STR + c0 + 1]       = __uint_as_float(f2tf(fmaxf(c1[mt][nt][1] + bb1, 0.f)));
            Hs[(r + 8) * HS_STR + c0]     = __uint_as_float(f2tf(fmaxf(c1[mt][nt][2] + bb0, 0.f)));
            Hs[(r + 8) * HS_STR + c0 + 1] = __uint_as_float(f2tf(fmaxf(c1[mt][nt][3] + bb1, 0.f)));
        }
    }

    // ---- GEMM2: Z[64x128] = H[64x256] @ W2[256x128], KC=16, 16 chunks ----
    float c2[2][4][4];
#pragma unroll
    for (int mt = 0; mt < 2; mt++)
#pragma unroll
        for (int nt = 0; nt < 4; nt++)
#pragma unroll
            for (int j = 0; j < 4; j++) c2[mt][nt][j] = 0.f;

    // prefetch + store W2 chunk 0 (Ws free: GEMM1 consumers synced above)
#pragma unroll
    for (int p = 0; p < 2; p++) {
        int idx4 = tid + p * 256;
        int row = idx4 >> 5, col4 = idx4 & 31;
        wreg[p] = *(const float4*)&W2[(size_t)row * 128 + col4 * 4];
    }
#pragma unroll
    for (int p = 0; p < 2; p++) {
        int idx4 = tid + p * 256;
        int row = idx4 >> 5, col4 = idx4 & 31;
        float* d = &Ws[row * W2_STR + col4 * 4];
        d[0] = __uint_as_float(f2tf(wreg[p].x));
        d[1] = __uint_as_float(f2tf(wreg[p].y));
        d[2] = __uint_as_float(f2tf(wreg[p].z));
        d[3] = __uint_as_float(f2tf(wreg[p].w));
    }
    __syncthreads();   // Hs + W2 chunk0 visible

    for (int kc = 0; kc < 16; kc++) {
        if (kc < 15) {
#pragma unroll
            for (int p = 0; p < 2; p++) {
                int idx4 = tid + p * 256;
                int row = idx4 >> 5, col4 = idx4 & 31;
                wreg[p] = *(const float4*)&W2[(size_t)((kc + 1) * 16 + row) * 128 + col4 * 4];
            }
        }
#pragma unroll
        for (int ks = 0; ks < 2; ks++) {
            int kl = ks * 8;
            int kg = kc * 16 + kl;
            unsigned a[2][4];
#pragma unroll
            for (int mt = 0; mt < 2; mt++) {
                int r = warp_m * 32 + mt * 16 + g;
                const float* x0 = &Hs[r * HS_STR + kg + t];
                const float* x8 = &Hs[(r + 8) * HS_STR + kg + t];
                a[mt][0] = __float_as_uint(x0[0]);
                a[mt][1] = __float_as_uint(x8[0]);
                a[mt][2] = __float_as_uint(x0[4]);
                a[mt][3] = __float_as_uint(x8[4]);
            }
#pragma unroll
            for (int nt = 0; nt < 4; nt++) {
                int col = warp_n * 32 + nt * 8 + g;
                unsigned b0 = __float_as_uint(Ws[(kl + t) * W2_STR + col]);
                unsigned b1r = __float_as_uint(Ws[(kl + t + 4) * W2_STR + col]);
                mma_tf32(c2[0][nt], a[0], b0, b1r);
                mma_tf32(c2[1][nt], a[1], b0, b1r);
            }
        }
        __syncthreads();
        if (kc < 15) {
#pragma unroll
            for (int p = 0; p < 2; p++) {
                int idx4 = tid + p * 256;
                int row = idx4 >> 5, col4 = idx4 & 31;
                float* d = &Ws[row * W2_STR + col4 * 4];
                d[0] = __uint_as_float(f2tf(wreg[p].x));
                d[1] = __uint_as_float(f2tf(wreg[p].y));
                d[2] = __uint_as_float(f2tf(wreg[p].z));
                d[3] = __uint_as_float(f2tf(wreg[p].w));
            }
            __syncthreads();
        }
    }

    // ---- epilogue2: bias, BN, [relu], residual, store ----
#pragma unroll
    for (int nt = 0; nt < 4; nt++) {
        int col = warp_n * 32 + nt * 8 + t * 2;
        float bv0 = __ldg(&b2[col]),        bv1 = __ldg(&b2[col + 1]);
        float gv0 = __ldg(&gamma[col]) * inv, gv1 = __ldg(&gamma[col + 1]) * inv;
        float ev0 = __ldg(&beta[col]),      ev1 = __ldg(&beta[col + 1]);
#pragma unroll
        for (int mt = 0; mt < 2; mt++) {
#pragma unroll
            for (int half = 0; half < 2; half++) {
                int row = warp_m * 32 + mt * 16 + g + half * 8;
                int node = base + row;
                if (node < N) {
                    float z0 = c2[mt][nt][half * 2]     + bv0;
                    float z1 = c2[mt][nt][half * 2 + 1] + bv1;
                    z0 = z0 * gv0 + ev0;
                    z1 = z1 * gv1 + ev1;
                    if (relu_out) { z0 = fmaxf(z0, 0.f); z1 = fmaxf(z1, 0.f); }
                    float2 hr = *(const float2*)&hin[(size_t)node * EMB + col];
                    float2 o = make_float2(z0 + hr.x, z1 + hr.y);
                    *(float2*)&out[(size_t)node * EMB + col] = o;
                }
            }
        }
    }
}

// ---------------- kernel 4: virtual-node MLP ----------------
__global__ __launch_bounds__(256) void k_vn_mlp(
    const float* __restrict__ vt, float* __restrict__ vn,
    const float* __restrict__ w1, const float* __restrict__ b1,
    const float* __restrict__ g1, const float* __restrict__ be1,
    const float* __restrict__ w2, const float* __restrict__ b2,
    const float* __restrict__ g2, const float* __restrict__ be2, float inv) {
    __shared__ float sv[EMB];
    __shared__ float sm1[HID];
    int g = blockIdx.x;
    int tid = threadIdx.x;
    if (tid < EMB) sv[tid] = vt[(size_t)g * EMB + tid] + vn[(size_t)g * EMB + tid];
    __syncthreads();
    {
        int j = tid;
        float s = b1[j];
#pragma unroll 8
        for (int k = 0; k < EMB; k++) s += sv[k] * w1[(size_t)k * HID + j];
        s = s * (g1[j] * inv) + be1[j];
        sm1[j] = fmaxf(s, 0.f);
    }
    __syncthreads();
    if (tid < EMB) {
        int c = tid;
        float s = b2[c];
#pragma unroll 8
        for (int j = 0; j < HID; j++) s += sm1[j] * w2[(size_t)j * EMB + c];
        s = s * (g2[c] * inv) + be2[c];
        vn[(size_t)g * EMB + c] += fmaxf(s, 0.f);
    }
}

// ---------------- host orchestration ----------------
extern "C" void kernel_launch(void* const* d_in, const int* in_sizes, int n_in,
                              void* d_out, int out_size) {
    if (n_in < 21) return;

    const float* input_feature = (const float*)d_in[0];
    const int* edge_index;
    const float* edge_attr;
    long long E;
    if ((long long)in_sizes[1] < (long long)in_sizes[2]) {
        edge_index = (const int*)d_in[1];
        edge_attr  = (const float*)d_in[2];
        E = in_sizes[1] / 2;
    } else {
        edge_index = (const int*)d_in[2];
        edge_attr  = (const float*)d_in[1];
        E = in_sizes[2] / 2;
    }
    const int* batch = (const int*)d_in[3];
    int N = in_sizes[0] / EMB;

    const float* vn_emb = (const float*)d_in[4];
    const float* cew = (const float*)d_in[5];
    const float* ceb = (const float*)d_in[6];
    const float* cw1 = (const float*)d_in[7];
    const float* cb1 = (const float*)d_in[8];
    const float* cw2 = (const float*)d_in[9];
    const float* cb2 = (const float*)d_in[10];
    const float* bng = (const float*)d_in[11];
    const float* bnb = (const float*)d_in[12];
    const float* vw1 = (const float*)d_in[13];
    const float* vb1 = (const float*)d_in[14];
    const float* vg1 = (const float*)d_in[15];
    const float* vbe1 = (const float*)d_in[16];
    const float* vw2 = (const float*)d_in[17];
    const float* vb2 = (const float*)d_in[18];
    const float* vg2 = (const float*)d_in[19];
    const float* vbe2 = (const float*)d_in[20];

    float* hin; float* agg; float* hbuf; float* vn; float* vt;
    cudaGetSymbolAddress((void**)&hin, g_hin);
    cudaGetSymbolAddress((void**)&agg, g_agg);
    cudaGetSymbolAddress((void**)&hbuf, g_h);
    cudaGetSymbolAddress((void**)&vn, g_vn);
    cudaGetSymbolAddress((void**)&vt, g_vt);

    cudaFuncSetAttribute(k_node_mlp, cudaFuncAttributeMaxDynamicSharedMemorySize,
                         MLP_SMEM_FLOATS * (int)sizeof(float));

    const float inv = 1.0f / sqrtf(1.0f + 1e-5f);

    k_init_vn<<<(NGRAPH * EMB + 255) / 256, 256>>>(vn_emb, vn);

    int nblk = (N + 63) / 64;
    int eblk = (int)((E + 31) / 32);

    const float* h = input_feature;
    for (int l = 0; l < NLAYER; l++) {
        int doVT = (l < NLAYER - 1);
        cudaMemsetAsync(agg, 0, (size_t)N * EMB * sizeof(float));
        if (doVT) cudaMemsetAsync(vt, 0, (size_t)NGRAPH * EMB * sizeof(float));

        k_hin_vt<<<nblk, dim3(32, 8)>>>(h, batch, vn, hin, vt, N, doVT);

        k_edge<<<eblk, 256>>>(hin, edge_attr, edge_index,
                              cew + (size_t)l * EDIM * EMB, ceb + (size_t)l * EMB,
                              agg, (int)E);

        float* outp = (l == NLAYER - 1) ? (float*)d_out : hbuf;
        k_node_mlp<<<nblk, 256, MLP_SMEM_FLOATS * (int)sizeof(float)>>>(
            hin, agg,
            cw1 + (size_t)l * EMB * HID, cb1 + (size_t)l * HID,
            cw2 + (size_t)l * HID * EMB, cb2 + (size_t)l * EMB,
            bng + (size_t)l * EMB, bnb + (size_t)l * EMB,
            outp, N, doVT ? 1 : 0, inv);

        if (doVT) {
            k_vn_mlp<<<NGRAPH, 256>>>(vt, vn,
                                      vw1 + (size_t)l * EMB * HID, vb1 + (size_t)l * HID,
                                      vg1 + (size_t)l * HID, vbe1 + (size_t)l * HID,
                                      vw2 + (size_t)l * HID * EMB, vb2 + (size_t)l * EMB,
                                      vg2 + (size_t)l * EMB, vbe2 + (size_t)l * EMB, inv);
        }
        h = outp;
    }
}

// round 4
// speedup vs baseline: 2.5104x; 1.2343x over previous
#include <cuda_runtime.h>
#include <cuda_bf16.h>
#include <math.h>

// ---------------- problem constants ----------------
#define EMB 128
#define HID 256
#define EDIM 16
#define NGRAPH 512
#define NLAYER 3
#define MAXN 100352
#define MAXE 600064

// ---------------- scratch (device globals) ----------------
__device__ float g_hin[(size_t)MAXN * EMB];
__device__ float g_agg[(size_t)MAXN * EMB];
__device__ float g_h  [(size_t)MAXN * EMB];
__device__ float g_vn [NGRAPH * EMB];
__device__ float g_vt [NGRAPH * EMB];

// ---------------- helpers ----------------
__device__ __forceinline__ void red_add_v4(float* p, float4 v) {
    asm volatile("red.global.add.v4.f32 [%0], {%1,%2,%3,%4};"
                 :: "l"(p), "f"(v.x), "f"(v.y), "f"(v.z), "f"(v.w) : "memory");
}
__device__ __forceinline__ unsigned f2tf(float f) {
    unsigned r; asm("cvt.rna.tf32.f32 %0, %1;" : "=r"(r) : "f"(f)); return r;
}
__device__ __forceinline__ void mma_tf32(float* c, const unsigned* a, unsigned b0, unsigned b1) {
    asm volatile("mma.sync.aligned.m16n8k8.row.col.f32.tf32.tf32.f32 "
                 "{%0,%1,%2,%3},{%4,%5,%6,%7},{%8,%9},{%0,%1,%2,%3};"
                 : "+f"(c[0]), "+f"(c[1]), "+f"(c[2]), "+f"(c[3])
                 : "r"(a[0]), "r"(a[1]), "r"(a[2]), "r"(a[3]), "r"(b0), "r"(b1));
}
__device__ __forceinline__ void cp_async16(float* smem, const float* gmem) {
    unsigned s = (unsigned)__cvta_generic_to_shared(smem);
    asm volatile("cp.async.cg.shared.global [%0], [%1], 16;" :: "r"(s), "l"(gmem));
}
#define CP_COMMIT() asm volatile("cp.async.commit_group;")
#define CP_WAIT1()  asm volatile("cp.async.wait_group 1;")
#define CP_WAIT0()  asm volatile("cp.async.wait_group 0;")

// ---------------- kernel 0: init vn ----------------
__global__ void k_init_vn(const float* __restrict__ vn_emb, float* __restrict__ vn) {
    int i = blockIdx.x * blockDim.x + threadIdx.x;
    if (i < NGRAPH * EMB) vn[i] = vn_emb[i & (EMB - 1)];
}

// ---------------- kernel 1: hin = h + vn[batch]; agg = 0; vt += segsum(hin) ----------------
__global__ void k_hin_vt(const float* __restrict__ h, const int* __restrict__ batch,
                         const float* __restrict__ vn, float* __restrict__ hin,
                         float* __restrict__ agg, float* __restrict__ vt,
                         int N, int doVT) {
    int lane = threadIdx.x;
    int row  = threadIdx.y;
    int base = blockIdx.x * 64;
    float4 acc = make_float4(0.f, 0.f, 0.f, 0.f);
    const float4 zero = make_float4(0.f, 0.f, 0.f, 0.f);
    int gcur = -1;
    for (int it = 0; it < 8; it++) {
        int i = base + it * 8 + row;
        if (i >= N) break;
        int g = batch[i];
        const float4 hv = *(const float4*)&h[(size_t)i * EMB + lane * 4];
        const float4 vv = *(const float4*)&vn[(size_t)g * EMB + lane * 4];
        float4 s = make_float4(hv.x + vv.x, hv.y + vv.y, hv.z + vv.z, hv.w + vv.w);
        *(float4*)&hin[(size_t)i * EMB + lane * 4] = s;
        *(float4*)&agg[(size_t)i * EMB + lane * 4] = zero;
        if (doVT) {
            if (g != gcur) {
                if (gcur >= 0) red_add_v4(&vt[(size_t)gcur * EMB + lane * 4], acc);
                acc = make_float4(0.f, 0.f, 0.f, 0.f);
                gcur = g;
            }
            acc.x += s.x; acc.y += s.y; acc.z += s.z; acc.w += s.w;
        }
    }
    if (doVT && gcur >= 0) red_add_v4(&vt[(size_t)gcur * EMB + lane * 4], acc);
}

// ---------------- kernel 2: edge conv (front-batched loads, 4 edges/warp) ----------------
__global__ __launch_bounds__(256) void k_edge(const float* __restrict__ hin,
                                              const float* __restrict__ ea,
                                              const int* __restrict__ eidx,
                                              const float* __restrict__ We,
                                              const float* __restrict__ be,
                                              float* __restrict__ agg, int E) {
    __shared__ float sW[EDIM * EMB];
    __shared__ float sb[EMB];
    int tid = threadIdx.x;
#pragma unroll
    for (int t = 0; t < 8; t++) sW[tid + 256 * t] = We[tid + 256 * t];
    if (tid < EMB) sb[tid] = be[tid];
    __syncthreads();

    int warp = tid >> 5, lane = tid & 31;
    long long ebase = (long long)blockIdx.x * 32 + warp * 4;
    if (ebase >= E) return;

    int srcs[4], dsts[4];
    float eav[4];
    bool val[4];
#pragma unroll
    for (int ew = 0; ew < 4; ew++) {
        long long e = ebase + ew;
        val[ew] = (e < E);
        if (val[ew]) {
            srcs[ew] = eidx[e];
            dsts[ew] = eidx[E + e];
            eav[ew]  = (lane < EDIM) ? __ldg(&ea[e * EDIM + lane]) : 0.f;
        } else { srcs[ew] = 0; dsts[ew] = 0; eav[ew] = 0.f; }
    }
    // front-batch the 4 gathers
    float4 x[4];
#pragma unroll
    for (int ew = 0; ew < 4; ew++)
        x[ew] = val[ew] ? *(const float4*)&hin[(size_t)srcs[ew] * EMB + lane * 4]
                        : make_float4(0.f, 0.f, 0.f, 0.f);

#pragma unroll
    for (int ew = 0; ew < 4; ew++) {
        if (!val[ew]) continue;
        float4 emb = *(const float4*)&sb[lane * 4];
#pragma unroll
        for (int k = 0; k < EDIM; k++) {
            float ek = __shfl_sync(0xffffffffu, eav[ew], k);
            float4 w = *(const float4*)&sW[k * EMB + lane * 4];
            emb.x += ek * w.x; emb.y += ek * w.y; emb.z += ek * w.z; emb.w += ek * w.w;
        }
        float4 m = make_float4(fmaxf(x[ew].x + emb.x, 0.f), fmaxf(x[ew].y + emb.y, 0.f),
                               fmaxf(x[ew].z + emb.z, 0.f), fmaxf(x[ew].w + emb.w, 0.f));
        red_add_v4(&agg[(size_t)dsts[ew] * EMB + lane * 4], m);
    }
}

// ---------------- kernel 3: tensor-core node MLP (tf32 mma, cp.async, occ=2) ----------------
// 64 nodes / CTA, 256 threads = 8 warps (warp grid 2m x 4n).
// Smem: UB = union(Xs 64x132 | Hs 64x260) + double-buffered weight chunks.
#define XS_STR 132
#define HS_STR 260
#define W1_STR 264
#define W2_STR 136
#define UB_FLOATS (64 * HS_STR)                  // 16640
#define WD_FLOATS (2 * 16 * W1_STR)              // 8448
#define MLP_SMEM_FLOATS (UB_FLOATS + WD_FLOATS)  // 25088 -> 100352 B

__global__ __launch_bounds__(256, 2) void k_node_mlp(
    const float* __restrict__ hin, const float* __restrict__ agg,
    const float* __restrict__ W1, const float* __restrict__ b1,
    const float* __restrict__ W2, const float* __restrict__ b2,
    const float* __restrict__ gamma, const float* __restrict__ beta,
    float* __restrict__ out, int N, int relu_out, float inv) {
    extern __shared__ float smf[];
    float* Xs = smf;                 // 64 x XS_STR (dies after GEMM1)
    float* Hs = smf;                 // 64 x HS_STR (union with Xs)
    float* Wd = smf + UB_FLOATS;     // 2 x 16 x W1_STR

    int tid = threadIdx.x;
    int wid = tid >> 5, lane = tid & 31;
    int g = lane >> 2, t = lane & 3;
    int warp_m = wid >> 2;
    int warp_n = wid & 3;
    int base = blockIdx.x * 64;

    // ---- stage X = tf32(hin + agg) ----
#pragma unroll
    for (int p = 0; p < 8; p++) {
        int li = tid + p * 256;
        int row = li >> 5;
        int c4 = (li & 31) * 4;
        int node = base + row;
        float4 v = make_float4(0.f, 0.f, 0.f, 0.f);
        if (node < N) {
            float4 a = *(const float4*)&hin[(size_t)node * EMB + c4];
            float4 b = *(const float4*)&agg[(size_t)node * EMB + c4];
            v = make_float4(a.x + b.x, a.y + b.y, a.z + b.z, a.w + b.w);
        }
        float* d = &Xs[row * XS_STR + c4];
        d[0] = __uint_as_float(f2tf(v.x));
        d[1] = __uint_as_float(f2tf(v.y));
        d[2] = __uint_as_float(f2tf(v.z));
        d[3] = __uint_as_float(f2tf(v.w));
    }

    // ---- GEMM1: [64x128]@[128x256], 8 chunks of K=16, cp.async double-buffered ----
    float c1[2][8][4];
#pragma unroll
    for (int mt = 0; mt < 2; mt++)
#pragma unroll
        for (int nt = 0; nt < 8; nt++)
#pragma unroll
            for (int j = 0; j < 4; j++) c1[mt][nt][j] = 0.f;

    {
        int idx_row = 0, idx_c4 = 0;
#pragma unroll
        for (int p = 0; p < 4; p++) {
            int idx4 = tid + p * 256;
            idx_row = idx4 >> 6; idx_c4 = idx4 & 63;
            cp_async16(&Wd[idx_row * W1_STR + idx_c4 * 4],
                       &W1[(size_t)idx_row * 256 + idx_c4 * 4]);
        }
        CP_COMMIT();
    }

    for (int kc = 0; kc < 8; kc++) {
        if (kc < 7) {
            float* db = Wd + ((kc + 1) & 1) * (16 * W1_STR);
#pragma unroll
            for (int p = 0; p < 4; p++) {
                int idx4 = tid + p * 256;
                int row = idx4 >> 6, c4 = idx4 & 63;
                cp_async16(&db[row * W1_STR + c4 * 4],
                           &W1[(size_t)((kc + 1) * 16 + row) * 256 + c4 * 4]);
            }
            CP_COMMIT();
            CP_WAIT1();
        } else {
            CP_WAIT0();
        }
        __syncthreads();
        const float* Wb = Wd + (kc & 1) * (16 * W1_STR);
#pragma unroll
        for (int ks = 0; ks < 2; ks++) {
            int kl = ks * 8;
            int kg = kc * 16 + kl;
            unsigned a[2][4];
#pragma unroll
            for (int mt = 0; mt < 2; mt++) {
                int r = warp_m * 32 + mt * 16 + g;
                const float* x0 = &Xs[r * XS_STR + kg + t];
                const float* x8 = &Xs[(r + 8) * XS_STR + kg + t];
                a[mt][0] = __float_as_uint(x0[0]);
                a[mt][1] = __float_as_uint(x8[0]);
                a[mt][2] = __float_as_uint(x0[4]);
                a[mt][3] = __float_as_uint(x8[4]);
            }
#pragma unroll
            for (int nt = 0; nt < 8; nt++) {
                int col = warp_n * 64 + nt * 8 + g;
                unsigned b0 = __float_as_uint(Wb[(kl + t) * W1_STR + col]);
                unsigned b1r = __float_as_uint(Wb[(kl + t + 4) * W1_STR + col]);
                mma_tf32(c1[0][nt], a[0], b0, b1r);
                mma_tf32(c1[1][nt], a[1], b0, b1r);
            }
        }
        __syncthreads();
    }

    // ---- epilogue1: bias + relu -> Hs (overwrites Xs union; safe after sync) ----
#pragma unroll
    for (int nt = 0; nt < 8; nt++) {
        int c0 = warp_n * 64 + nt * 8 + t * 2;
        float bb0 = __ldg(&b1[c0]);
        float bb1 = __ldg(&b1[c0 + 1]);
#pragma unroll
        for (int mt = 0; mt < 2; mt++) {
            int r = warp_m * 32 + mt * 16 + g;
            Hs[r * HS_STR + c0]           = __uint_as_float(f2tf(fmaxf(c1[mt][nt][0] + bb0, 0.f)));
            Hs[r * HS_STR + c0 + 1]       = __uint_as_float(f2tf(fmaxf(c1[mt][nt][1] + bb1, 0.f)));
            Hs[(r + 8) * HS_STR + c0]     = __uint_as_float(f2tf(fmaxf(c1[mt][nt][2] + bb0, 0.f)));
            Hs[(r + 8) * HS_STR + c0 + 1] = __uint_as_float(f2tf(fmaxf(c1[mt][nt][3] + bb1, 0.f)));
        }
    }

    // ---- GEMM2: [64x256]@[256x128], 16 chunks of K=16 ----
    float c2[2][4][4];
#pragma unroll
    for (int mt = 0; mt < 2; mt++)
#pragma unroll
        for (int nt = 0; nt < 4; nt++)
#pragma unroll
            for (int j = 0; j < 4; j++) c2[mt][nt][j] = 0.f;

    {
#pragma unroll
        for (int p = 0; p < 2; p++) {
            int idx4 = tid + p * 256;
            int row = idx4 >> 5, c4 = idx4 & 31;
            cp_async16(&Wd[row * W2_STR + c4 * 4],
                       &W2[(size_t)row * 128 + c4 * 4]);
        }
        CP_COMMIT();
    }

    for (int kc = 0; kc < 16; kc++) {
        if (kc < 15) {
            float* db = Wd + ((kc + 1) & 1) * (16 * W2_STR);
#pragma unroll
            for (int p = 0; p < 2; p++) {
                int idx4 = tid + p * 256;
                int row = idx4 >> 5, c4 = idx4 & 31;
                cp_async16(&db[row * W2_STR + c4 * 4],
                           &W2[(size_t)((kc + 1) * 16 + row) * 128 + c4 * 4]);
            }
            CP_COMMIT();
            CP_WAIT1();
        } else {
            CP_WAIT0();
        }
        __syncthreads();
        const float* Wb = Wd + (kc & 1) * (16 * W2_STR);
#pragma unroll
        for (int ks = 0; ks < 2; ks++) {
            int kl = ks * 8;
            int kg = kc * 16 + kl;
            unsigned a[2][4];
#pragma unroll
            for (int mt = 0; mt < 2; mt++) {
                int r = warp_m * 32 + mt * 16 + g;
                const float* x0 = &Hs[r * HS_STR + kg + t];
                const float* x8 = &Hs[(r + 8) * HS_STR + kg + t];
                a[mt][0] = __float_as_uint(x0[0]);
                a[mt][1] = __float_as_uint(x8[0]);
                a[mt][2] = __float_as_uint(x0[4]);
                a[mt][3] = __float_as_uint(x8[4]);
            }
#pragma unroll
            for (int nt = 0; nt < 4; nt++) {
                int col = warp_n * 32 + nt * 8 + g;
                unsigned b0 = __float_as_uint(Wb[(kl + t) * W2_STR + col]);
                unsigned b1r = __float_as_uint(Wb[(kl + t + 4) * W2_STR + col]);
                mma_tf32(c2[0][nt], a[0], b0, b1r);
                mma_tf32(c2[1][nt], a[1], b0, b1r);
            }
        }
        __syncthreads();
    }

    // ---- epilogue2: bias, BN, [relu], residual ----
#pragma unroll
    for (int nt = 0; nt < 4; nt++) {
        int col = warp_n * 32 + nt * 8 + t * 2;
        float bv0 = __ldg(&b2[col]),          bv1 = __ldg(&b2[col + 1]);
        float gv0 = __ldg(&gamma[col]) * inv, gv1 = __ldg(&gamma[col + 1]) * inv;
        float ev0 = __ldg(&beta[col]),        ev1 = __ldg(&beta[col + 1]);
#pragma unroll
        for (int mt = 0; mt < 2; mt++) {
#pragma unroll
            for (int half = 0; half < 2; half++) {
                int row = warp_m * 32 + mt * 16 + g + half * 8;
                int node = base + row;
                if (node < N) {
                    float z0 = c2[mt][nt][half * 2]     + bv0;
                    float z1 = c2[mt][nt][half * 2 + 1] + bv1;
                    z0 = z0 * gv0 + ev0;
                    z1 = z1 * gv1 + ev1;
                    if (relu_out) { z0 = fmaxf(z0, 0.f); z1 = fmaxf(z1, 0.f); }
                    float2 hr = *(const float2*)&hin[(size_t)node * EMB + col];
                    float2 o = make_float2(z0 + hr.x, z1 + hr.y);
                    *(float2*)&out[(size_t)node * EMB + col] = o;
                }
            }
        }
    }
}

// ---------------- kernel 4: virtual-node MLP ----------------
__global__ __launch_bounds__(256) void k_vn_mlp(
    const float* __restrict__ vt, float* __restrict__ vn,
    const float* __restrict__ w1, const float* __restrict__ b1,
    const float* __restrict__ g1, const float* __restrict__ be1,
    const float* __restrict__ w2, const float* __restrict__ b2,
    const float* __restrict__ g2, const float* __restrict__ be2, float inv) {
    __shared__ float sv[EMB];
    __shared__ float sm1[HID];
    int g = blockIdx.x;
    int tid = threadIdx.x;
    if (tid < EMB) sv[tid] = vt[(size_t)g * EMB + tid] + vn[(size_t)g * EMB + tid];
    __syncthreads();
    {
        int j = tid;
        float s = b1[j];
#pragma unroll 8
        for (int k = 0; k < EMB; k++) s += sv[k] * w1[(size_t)k * HID + j];
        s = s * (g1[j] * inv) + be1[j];
        sm1[j] = fmaxf(s, 0.f);
    }
    __syncthreads();
    if (tid < EMB) {
        int c = tid;
        float s = b2[c];
#pragma unroll 8
        for (int j = 0; j < HID; j++) s += sm1[j] * w2[(size_t)j * EMB + c];
        s = s * (g2[c] * inv) + be2[c];
        vn[(size_t)g * EMB + c] += fmaxf(s, 0.f);
    }
}

// ---------------- host orchestration ----------------
extern "C" void kernel_launch(void* const* d_in, const int* in_sizes, int n_in,
                              void* d_out, int out_size) {
    if (n_in < 21) return;

    const float* input_feature = (const float*)d_in[0];
    const int* edge_index;
    const float* edge_attr;
    long long E;
    if ((long long)in_sizes[1] < (long long)in_sizes[2]) {
        edge_index = (const int*)d_in[1];
        edge_attr  = (const float*)d_in[2];
        E = in_sizes[1] / 2;
    } else {
        edge_index = (const int*)d_in[2];
        edge_attr  = (const float*)d_in[1];
        E = in_sizes[2] / 2;
    }
    const int* batch = (const int*)d_in[3];
    int N = in_sizes[0] / EMB;

    const float* vn_emb = (const float*)d_in[4];
    const float* cew = (const float*)d_in[5];
    const float* ceb = (const float*)d_in[6];
    const float* cw1 = (const float*)d_in[7];
    const float* cb1 = (const float*)d_in[8];
    const float* cw2 = (const float*)d_in[9];
    const float* cb2 = (const float*)d_in[10];
    const float* bng = (const float*)d_in[11];
    const float* bnb = (const float*)d_in[12];
    const float* vw1 = (const float*)d_in[13];
    const float* vb1 = (const float*)d_in[14];
    const float* vg1 = (const float*)d_in[15];
    const float* vbe1 = (const float*)d_in[16];
    const float* vw2 = (const float*)d_in[17];
    const float* vb2 = (const float*)d_in[18];
    const float* vg2 = (const float*)d_in[19];
    const float* vbe2 = (const float*)d_in[20];

    float* hin; float* agg; float* hbuf; float* vn; float* vt;
    cudaGetSymbolAddress((void**)&hin, g_hin);
    cudaGetSymbolAddress((void**)&agg, g_agg);
    cudaGetSymbolAddress((void**)&hbuf, g_h);
    cudaGetSymbolAddress((void**)&vn, g_vn);
    cudaGetSymbolAddress((void**)&vt, g_vt);

    cudaFuncSetAttribute(k_node_mlp, cudaFuncAttributeMaxDynamicSharedMemorySize,
                         MLP_SMEM_FLOATS * (int)sizeof(float));

    const float inv = 1.0f / sqrtf(1.0f + 1e-5f);

    k_init_vn<<<(NGRAPH * EMB + 255) / 256, 256>>>(vn_emb, vn);

    int nblk = (N + 63) / 64;
    int eblk = (int)((E + 31) / 32);

    const float* h = input_feature;
    for (int l = 0; l < NLAYER; l++) {
        int doVT = (l < NLAYER - 1);
        if (doVT) cudaMemsetAsync(vt, 0, (size_t)NGRAPH * EMB * sizeof(float));

        k_hin_vt<<<nblk, dim3(32, 8)>>>(h, batch, vn, hin, agg, vt, N, doVT);

        k_edge<<<eblk, 256>>>(hin, edge_attr, edge_index,
                              cew + (size_t)l * EDIM * EMB, ceb + (size_t)l * EMB,
                              agg, (int)E);

        float* outp = (l == NLAYER - 1) ? (float*)d_out : hbuf;
        k_node_mlp<<<nblk, 256, MLP_SMEM_FLOATS * (int)sizeof(float)>>>(
            hin, agg,
            cw1 + (size_t)l * EMB * HID, cb1 + (size_t)l * HID,
            cw2 + (size_t)l * HID * EMB, cb2 + (size_t)l * EMB,
            bng + (size_t)l * EMB, bnb + (size_t)l * EMB,
            outp, N, doVT ? 1 : 0, inv);

        if (doVT) {
            k_vn_mlp<<<NGRAPH, 256>>>(vt, vn,
                                      vw1 + (size_t)l * EMB * HID, vb1 + (size_t)l * HID,
                                      vg1 + (size_t)l * HID, vbe1 + (size_t)l * HID,
                                      vw2 + (size_t)l * HID * EMB, vb2 + (size_t)l * EMB,
                                      vg2 + (size_t)l * EMB, vbe2 + (size_t)l * EMB, inv);
        }
        h = outp;
    }
}

// round 5
// speedup vs baseline: 2.6878x; 1.0707x over previous
#include <cuda_runtime.h>
#include <cuda_bf16.h>
#include <math.h>

// ---------------- problem constants ----------------
#define EMB 128
#define HID 256
#define EDIM 16
#define NGRAPH 512
#define NLAYER 3
#define MAXN 100352
#define MAXE 600064

// ---------------- scratch (device globals) ----------------
__device__ float g_hin[(size_t)MAXN * EMB];
__device__ float g_agg[(size_t)MAXN * EMB];
__device__ float g_h  [(size_t)MAXN * EMB];
__device__ float g_vn [NGRAPH * EMB];
__device__ float g_vt [NGRAPH * EMB];
// CSR scratch
__device__ int g_deg [MAXN];
__device__ int g_off [MAXN + 1];
__device__ int g_cur [MAXN];
__device__ int g_part[256];
__device__ int g_eids[MAXE];

// ---------------- helpers ----------------
__device__ __forceinline__ void red_add_v4(float* p, float4 v) {
    asm volatile("red.global.add.v4.f32 [%0], {%1,%2,%3,%4};"
                 :: "l"(p), "f"(v.x), "f"(v.y), "f"(v.z), "f"(v.w) : "memory");
}
__device__ __forceinline__ unsigned f2tf(float f) {
    unsigned r; asm("cvt.rna.tf32.f32 %0, %1;" : "=r"(r) : "f"(f)); return r;
}
__device__ __forceinline__ void mma_tf32(float* c, const unsigned* a, unsigned b0, unsigned b1) {
    asm volatile("mma.sync.aligned.m16n8k8.row.col.f32.tf32.tf32.f32 "
                 "{%0,%1,%2,%3},{%4,%5,%6,%7},{%8,%9},{%0,%1,%2,%3};"
                 : "+f"(c[0]), "+f"(c[1]), "+f"(c[2]), "+f"(c[3])
                 : "r"(a[0]), "r"(a[1]), "r"(a[2]), "r"(a[3]), "r"(b0), "r"(b1));
}
__device__ __forceinline__ void cp_async16(float* smem, const float* gmem) {
    unsigned s = (unsigned)__cvta_generic_to_shared(smem);
    asm volatile("cp.async.cg.shared.global [%0], [%1], 16;" :: "r"(s), "l"(gmem));
}
#define CP_COMMIT() asm volatile("cp.async.commit_group;")
#define CP_WAIT1()  asm volatile("cp.async.wait_group 1;")
#define CP_WAIT0()  asm volatile("cp.async.wait_group 0;")

// ================= CSR build (once per launch) =================
__global__ void k_count(const int* __restrict__ eidx, int* __restrict__ deg, int E) {
    int e = blockIdx.x * blockDim.x + threadIdx.x;
    if (e < E) atomicAdd(&deg[eidx[E + e]], 1);
}

// block exclusive scan of deg -> off (local), block totals -> part. 512 thr.
__global__ void k_scan1(const int* __restrict__ deg, int* __restrict__ off,
                        int* __restrict__ part, int N) {
    __shared__ int wsum[16];
    int i = blockIdx.x * 512 + threadIdx.x;
    int lane = threadIdx.x & 31, w = threadIdx.x >> 5;
    int v = (i < N) ? deg[i] : 0;
    int x = v;
#pragma unroll
    for (int d = 1; d < 32; d <<= 1) { int y = __shfl_up_sync(0xffffffffu, x, d); if (lane >= d) x += y; }
    if (lane == 31) wsum[w] = x;
    __syncthreads();
    if (w == 0) {
        int s = (lane < 16) ? wsum[lane] : 0;
#pragma unroll
        for (int d = 1; d < 16; d <<= 1) { int y = __shfl_up_sync(0xffffffffu, s, d); if (lane >= d) s += y; }
        if (lane < 16) wsum[lane] = s;
    }
    __syncthreads();
    int base = (w > 0) ? wsum[w - 1] : 0;
    if (i < N) off[i] = base + x - v;
    if (threadIdx.x == 0) part[blockIdx.x] = wsum[15];
}

// exclusive scan of part[256] in one block
__global__ void k_scan2(int* __restrict__ part) {
    __shared__ int wsum[8];
    int tid = threadIdx.x;  // 256 threads
    int lane = tid & 31, w = tid >> 5;
    int v = part[tid];
    int x = v;
#pragma unroll
    for (int d = 1; d < 32; d <<= 1) { int y = __shfl_up_sync(0xffffffffu, x, d); if (lane >= d) x += y; }
    if (lane == 31) wsum[w] = x;
    __syncthreads();
    if (w == 0) {
        int s = (lane < 8) ? wsum[lane] : 0;
#pragma unroll
        for (int d = 1; d < 8; d <<= 1) { int y = __shfl_up_sync(0xffffffffu, s, d); if (lane >= d) s += y; }
        if (lane < 8) wsum[lane] = s;
    }
    __syncthreads();
    int base = (w > 0) ? wsum[w - 1] : 0;
    part[tid] = base + x - v;
}

__global__ void k_scan3(int* __restrict__ off, int* __restrict__ cur,
                        const int* __restrict__ part, int N, int E) {
    int i = blockIdx.x * 512 + threadIdx.x;
    if (i < N) {
        int o = off[i] + part[blockIdx.x];
        off[i] = o;
        cur[i] = o;
    }
    if (i == 0) off[N] = E;
}

__global__ void k_scatter(const int* __restrict__ eidx, int* __restrict__ cur,
                          int* __restrict__ eids, int E) {
    int e = blockIdx.x * blockDim.x + threadIdx.x;
    if (e < E) {
        int pos = atomicAdd(&cur[eidx[E + e]], 1);
        eids[pos] = e;
    }
}

// ---------------- kernel 0: init vn ----------------
__global__ void k_init_vn(const float* __restrict__ vn_emb, float* __restrict__ vn) {
    int i = blockIdx.x * blockDim.x + threadIdx.x;
    if (i < NGRAPH * EMB) vn[i] = vn_emb[i & (EMB - 1)];
}

// ---------------- kernel 1: hin = h + vn[batch]; vt += segsum(hin) ----------------
__global__ void k_hin_vt(const float* __restrict__ h, const int* __restrict__ batch,
                         const float* __restrict__ vn, float* __restrict__ hin,
                         float* __restrict__ vt, int N, int doVT) {
    int lane = threadIdx.x;
    int row  = threadIdx.y;
    int base = blockIdx.x * 64;
    float4 acc = make_float4(0.f, 0.f, 0.f, 0.f);
    int gcur = -1;
    for (int it = 0; it < 8; it++) {
        int i = base + it * 8 + row;
        if (i >= N) break;
        int g = batch[i];
        const float4 hv = *(const float4*)&h[(size_t)i * EMB + lane * 4];
        const float4 vv = *(const float4*)&vn[(size_t)g * EMB + lane * 4];
        float4 s = make_float4(hv.x + vv.x, hv.y + vv.y, hv.z + vv.z, hv.w + vv.w);
        *(float4*)&hin[(size_t)i * EMB + lane * 4] = s;
        if (doVT) {
            if (g != gcur) {
                if (gcur >= 0) red_add_v4(&vt[(size_t)gcur * EMB + lane * 4], acc);
                acc = make_float4(0.f, 0.f, 0.f, 0.f);
                gcur = g;
            }
            acc.x += s.x; acc.y += s.y; acc.z += s.z; acc.w += s.w;
        }
    }
    if (doVT && gcur >= 0) red_add_v4(&vt[(size_t)gcur * EMB + lane * 4], acc);
}

// ---------------- kernel 2: CSR aggregation (no atomics) ----------------
// warp per destination node; walk incident edges; acc += relu(hin[src] + edge_emb); one store.
__global__ __launch_bounds__(256) void k_agg_csr(
    const float* __restrict__ hin, const float* __restrict__ ea,
    const int* __restrict__ srcarr, const int* __restrict__ off,
    const int* __restrict__ eids, const float* __restrict__ We,
    const float* __restrict__ be, float* __restrict__ agg, int N) {
    __shared__ float sW[EDIM * EMB];
    __shared__ float sb[EMB];
    int tid = threadIdx.x;
#pragma unroll
    for (int t = 0; t < 8; t++) sW[tid + 256 * t] = We[tid + 256 * t];
    if (tid < EMB) sb[tid] = be[tid];
    __syncthreads();

    int lane = tid & 31;
    int node = blockIdx.x * 8 + (tid >> 5);
    if (node >= N) return;
    int beg = off[node], end = off[node + 1];

    float4 acc = make_float4(0.f, 0.f, 0.f, 0.f);
    const float4 bias = *(const float4*)&sb[lane * 4];
    int p = beg;

    // unrolled-by-2 to overlap eid->src/ea indirection latency
    for (; p + 2 <= end; p += 2) {
        int e0 = eids[p], e1 = eids[p + 1];
        int s0 = srcarr[e0], s1 = srcarr[e1];
        float a0 = (lane < EDIM) ? __ldg(&ea[(size_t)e0 * EDIM + lane]) : 0.f;
        float a1 = (lane < EDIM) ? __ldg(&ea[(size_t)e1 * EDIM + lane]) : 0.f;
        float4 x0 = *(const float4*)&hin[(size_t)s0 * EMB + lane * 4];
        float4 x1 = *(const float4*)&hin[(size_t)s1 * EMB + lane * 4];
        float4 m0 = bias, m1 = bias;
#pragma unroll
        for (int k = 0; k < EDIM; k++) {
            float e0k = __shfl_sync(0xffffffffu, a0, k);
            float e1k = __shfl_sync(0xffffffffu, a1, k);
            float4 w = *(const float4*)&sW[k * EMB + lane * 4];
            m0.x += e0k * w.x; m0.y += e0k * w.y; m0.z += e0k * w.z; m0.w += e0k * w.w;
            m1.x += e1k * w.x; m1.y += e1k * w.y; m1.z += e1k * w.z; m1.w += e1k * w.w;
        }
        acc.x += fmaxf(x0.x + m0.x, 0.f) + fmaxf(x1.x + m1.x, 0.f);
        acc.y += fmaxf(x0.y + m0.y, 0.f) + fmaxf(x1.y + m1.y, 0.f);
        acc.z += fmaxf(x0.z + m0.z, 0.f) + fmaxf(x1.z + m1.z, 0.f);
        acc.w += fmaxf(x0.w + m0.w, 0.f) + fmaxf(x1.w + m1.w, 0.f);
    }
    if (p < end) {
        int e0 = eids[p];
        int s0 = srcarr[e0];
        float a0 = (lane < EDIM) ? __ldg(&ea[(size_t)e0 * EDIM + lane]) : 0.f;
        float4 x0 = *(const float4*)&hin[(size_t)s0 * EMB + lane * 4];
        float4 m0 = bias;
#pragma unroll
        for (int k = 0; k < EDIM; k++) {
            float e0k = __shfl_sync(0xffffffffu, a0, k);
            float4 w = *(const float4*)&sW[k * EMB + lane * 4];
            m0.x += e0k * w.x; m0.y += e0k * w.y; m0.z += e0k * w.z; m0.w += e0k * w.w;
        }
        acc.x += fmaxf(x0.x + m0.x, 0.f);
        acc.y += fmaxf(x0.y + m0.y, 0.f);
        acc.z += fmaxf(x0.z + m0.z, 0.f);
        acc.w += fmaxf(x0.w + m0.w, 0.f);
    }
    *(float4*)&agg[(size_t)node * EMB + lane * 4] = acc;
}

// ---------------- kernel 3: tensor-core node MLP (tf32 mma, cp.async, occ=2) ----------------
#define XS_STR 132
#define HS_STR 260
#define W1_STR 264
#define W2_STR 136
#define UB_FLOATS (64 * HS_STR)
#define WD_FLOATS (2 * 16 * W1_STR)
#define MLP_SMEM_FLOATS (UB_FLOATS + WD_FLOATS)

__global__ __launch_bounds__(256, 2) void k_node_mlp(
    const float* __restrict__ hin, const float* __restrict__ agg,
    const float* __restrict__ W1, const float* __restrict__ b1,
    const float* __restrict__ W2, const float* __restrict__ b2,
    const float* __restrict__ gamma, const float* __restrict__ beta,
    float* __restrict__ out, int N, int relu_out, float inv) {
    extern __shared__ float smf[];
    float* Xs = smf;
    float* Hs = smf;
    float* Wd = smf + UB_FLOATS;

    int tid = threadIdx.x;
    int wid = tid >> 5, lane = tid & 31;
    int g = lane >> 2, t = lane & 3;
    int warp_m = wid >> 2;
    int warp_n = wid & 3;
    int base = blockIdx.x * 64;

#pragma unroll
    for (int p = 0; p < 8; p++) {
        int li = tid + p * 256;
        int row = li >> 5;
        int c4 = (li & 31) * 4;
        int node = base + row;
        float4 v = make_float4(0.f, 0.f, 0.f, 0.f);
        if (node < N) {
            float4 a = *(const float4*)&hin[(size_t)node * EMB + c4];
            float4 b = *(const float4*)&agg[(size_t)node * EMB + c4];
            v = make_float4(a.x + b.x, a.y + b.y, a.z + b.z, a.w + b.w);
        }
        float* d = &Xs[row * XS_STR + c4];
        d[0] = __uint_as_float(f2tf(v.x));
        d[1] = __uint_as_float(f2tf(v.y));
        d[2] = __uint_as_float(f2tf(v.z));
        d[3] = __uint_as_float(f2tf(v.w));
    }

    float c1[2][8][4];
#pragma unroll
    for (int mt = 0; mt < 2; mt++)
#pragma unroll
        for (int nt = 0; nt < 8; nt++)
#pragma unroll
            for (int j = 0; j < 4; j++) c1[mt][nt][j] = 0.f;

    {
#pragma unroll
        for (int p = 0; p < 4; p++) {
            int idx4 = tid + p * 256;
            int row = idx4 >> 6, c4 = idx4 & 63;
            cp_async16(&Wd[row * W1_STR + c4 * 4], &W1[(size_t)row * 256 + c4 * 4]);
        }
        CP_COMMIT();
    }

    for (int kc = 0; kc < 8; kc++) {
        if (kc < 7) {
            float* db = Wd + ((kc + 1) & 1) * (16 * W1_STR);
#pragma unroll
            for (int p = 0; p < 4; p++) {
                int idx4 = tid + p * 256;
                int row = idx4 >> 6, c4 = idx4 & 63;
                cp_async16(&db[row * W1_STR + c4 * 4],
                           &W1[(size_t)((kc + 1) * 16 + row) * 256 + c4 * 4]);
            }
            CP_COMMIT();
            CP_WAIT1();
        } else {
            CP_WAIT0();
        }
        __syncthreads();
        const float* Wb = Wd + (kc & 1) * (16 * W1_STR);
#pragma unroll
        for (int ks = 0; ks < 2; ks++) {
            int kl = ks * 8;
            int kg = kc * 16 + kl;
            unsigned a[2][4];
#pragma unroll
            for (int mt = 0; mt < 2; mt++) {
                int r = warp_m * 32 + mt * 16 + g;
                const float* x0 = &Xs[r * XS_STR + kg + t];
                const float* x8 = &Xs[(r + 8) * XS_STR + kg + t];
                a[mt][0] = __float_as_uint(x0[0]);
                a[mt][1] = __float_as_uint(x8[0]);
                a[mt][2] = __float_as_uint(x0[4]);
                a[mt][3] = __float_as_uint(x8[4]);
            }
#pragma unroll
            for (int nt = 0; nt < 8; nt++) {
                int col = warp_n * 64 + nt * 8 + g;
                unsigned b0 = __float_as_uint(Wb[(kl + t) * W1_STR + col]);
                unsigned b1r = __float_as_uint(Wb[(kl + t + 4) * W1_STR + col]);
                mma_tf32(c1[0][nt], a[0], b0, b1r);
                mma_tf32(c1[1][nt], a[1], b0, b1r);
            }
        }
        __syncthreads();
    }

#pragma unroll
    for (int nt = 0; nt < 8; nt++) {
        int c0 = warp_n * 64 + nt * 8 + t * 2;
        float bb0 = __ldg(&b1[c0]);
        float bb1 = __ldg(&b1[c0 + 1]);
#pragma unroll
        for (int mt = 0; mt < 2; mt++) {
            int r = warp_m * 32 + mt * 16 + g;
            Hs[r * HS_STR + c0]           = __uint_as_float(f2tf(fmaxf(c1[mt][nt][0] + bb0, 0.f)));
            Hs[r * HS_STR + c0 + 1]       = __uint_as_float(f2tf(fmaxf(c1[mt][nt][1] + bb1, 0.f)));
            Hs[(r + 8) * HS_STR + c0]     = __uint_as_float(f2tf(fmaxf(c1[mt][nt][2] + bb0, 0.f)));
            Hs[(r + 8) * HS_STR + c0 + 1] = __uint_as_float(f2tf(fmaxf(c1[mt][nt][3] + bb1, 0.f)));
        }
    }

    float c2[2][4][4];
#pragma unroll
    for (int mt = 0; mt < 2; mt++)
#pragma unroll
        for (int nt = 0; nt < 4; nt++)
#pragma unroll
            for (int j = 0; j < 4; j++) c2[mt][nt][j] = 0.f;

    {
#pragma unroll
        for (int p = 0; p < 2; p++) {
            int idx4 = tid + p * 256;
            int row = idx4 >> 5, c4 = idx4 & 31;
            cp_async16(&Wd[row * W2_STR + c4 * 4], &W2[(size_t)row * 128 + c4 * 4]);
        }
        CP_COMMIT();
    }

    for (int kc = 0; kc < 16; kc++) {
        if (kc < 15) {
            float* db = Wd + ((kc + 1) & 1) * (16 * W2_STR);
#pragma unroll
            for (int p = 0; p < 2; p++) {
                int idx4 = tid + p * 256;
                int row = idx4 >> 5, c4 = idx4 & 31;
                cp_async16(&db[row * W2_STR + c4 * 4],
                           &W2[(size_t)((kc + 1) * 16 + row) * 128 + c4 * 4]);
            }
            CP_COMMIT();
            CP_WAIT1();
        } else {
            CP_WAIT0();
        }
        __syncthreads();
        const float* Wb = Wd + (kc & 1) * (16 * W2_STR);
#pragma unroll
        for (int ks = 0; ks < 2; ks++) {
            int kl = ks * 8;
            int kg = kc * 16 + kl;
            unsigned a[2][4];
#pragma unroll
            for (int mt = 0; mt < 2; mt++) {
                int r = warp_m * 32 + mt * 16 + g;
                const float* x0 = &Hs[r * HS_STR + kg + t];
                const float* x8 = &Hs[(r + 8) * HS_STR + kg + t];
                a[mt][0] = __float_as_uint(x0[0]);
                a[mt][1] = __float_as_uint(x8[0]);
                a[mt][2] = __float_as_uint(x0[4]);
                a[mt][3] = __float_as_uint(x8[4]);
            }
#pragma unroll
            for (int nt = 0; nt < 4; nt++) {
                int col = warp_n * 32 + nt * 8 + g;
                unsigned b0 = __float_as_uint(Wb[(kl + t) * W2_STR + col]);
                unsigned b1r = __float_as_uint(Wb[(kl + t + 4) * W2_STR + col]);
                mma_tf32(c2[0][nt], a[0], b0, b1r);
                mma_tf32(c2[1][nt], a[1], b0, b1r);
            }
        }
        __syncthreads();
    }

#pragma unroll
    for (int nt = 0; nt < 4; nt++) {
        int col = warp_n * 32 + nt * 8 + t * 2;
        float bv0 = __ldg(&b2[col]),          bv1 = __ldg(&b2[col + 1]);
        float gv0 = __ldg(&gamma[col]) * inv, gv1 = __ldg(&gamma[col + 1]) * inv;
        float ev0 = __ldg(&beta[col]),        ev1 = __ldg(&beta[col + 1]);
#pragma unroll
        for (int mt = 0; mt < 2; mt++) {
#pragma unroll
            for (int half = 0; half < 2; half++) {
                int row = warp_m * 32 + mt * 16 + g + half * 8;
                int node = base + row;
                if (node < N) {
                    float z0 = c2[mt][nt][half * 2]     + bv0;
                    float z1 = c2[mt][nt][half * 2 + 1] + bv1;
                    z0 = z0 * gv0 + ev0;
                    z1 = z1 * gv1 + ev1;
                    if (relu_out) { z0 = fmaxf(z0, 0.f); z1 = fmaxf(z1, 0.f); }
                    float2 hr = *(const float2*)&hin[(size_t)node * EMB + col];
                    float2 o = make_float2(z0 + hr.x, z1 + hr.y);
                    *(float2*)&out[(size_t)node * EMB + col] = o;
                }
            }
        }
    }
}

// ---------------- kernel 4: virtual-node MLP ----------------
__global__ __launch_bounds__(256) void k_vn_mlp(
    const float* __restrict__ vt, float* __restrict__ vn,
    const float* __restrict__ w1, const float* __restrict__ b1,
    const float* __restrict__ g1, const float* __restrict__ be1,
    const float* __restrict__ w2, const float* __restrict__ b2,
    const float* __restrict__ g2, const float* __restrict__ be2, float inv) {
    __shared__ float sv[EMB];
    __shared__ float sm1[HID];
    int g = blockIdx.x;
    int tid = threadIdx.x;
    if (tid < EMB) sv[tid] = vt[(size_t)g * EMB + tid] + vn[(size_t)g * EMB + tid];
    __syncthreads();
    {
        int j = tid;
        float s = b1[j];
#pragma unroll 8
        for (int k = 0; k < EMB; k++) s += sv[k] * w1[(size_t)k * HID + j];
        s = s * (g1[j] * inv) + be1[j];
        sm1[j] = fmaxf(s, 0.f);
    }
    __syncthreads();
    if (tid < EMB) {
        int c = tid;
        float s = b2[c];
#pragma unroll 8
        for (int j = 0; j < HID; j++) s += sm1[j] * w2[(size_t)j * EMB + c];
        s = s * (g2[c] * inv) + be2[c];
        vn[(size_t)g * EMB + c] += fmaxf(s, 0.f);
    }
}

// ---------------- host orchestration ----------------
extern "C" void kernel_launch(void* const* d_in, const int* in_sizes, int n_in,
                              void* d_out, int out_size) {
    if (n_in < 21) return;

    const float* input_feature = (const float*)d_in[0];
    const int* edge_index;
    const float* edge_attr;
    long long E;
    if ((long long)in_sizes[1] < (long long)in_sizes[2]) {
        edge_index = (const int*)d_in[1];
        edge_attr  = (const float*)d_in[2];
        E = in_sizes[1] / 2;
    } else {
        edge_index = (const int*)d_in[2];
        edge_attr  = (const float*)d_in[1];
        E = in_sizes[2] / 2;
    }
    const int* batch = (const int*)d_in[3];
    int N = in_sizes[0] / EMB;

    const float* vn_emb = (const float*)d_in[4];
    const float* cew = (const float*)d_in[5];
    const float* ceb = (const float*)d_in[6];
    const float* cw1 = (const float*)d_in[7];
    const float* cb1 = (const float*)d_in[8];
    const float* cw2 = (const float*)d_in[9];
    const float* cb2 = (const float*)d_in[10];
    const float* bng = (const float*)d_in[11];
    const float* bnb = (const float*)d_in[12];
    const float* vw1 = (const float*)d_in[13];
    const float* vb1 = (const float*)d_in[14];
    const float* vg1 = (const float*)d_in[15];
    const float* vbe1 = (const float*)d_in[16];
    const float* vw2 = (const float*)d_in[17];
    const float* vb2 = (const float*)d_in[18];
    const float* vg2 = (const float*)d_in[19];
    const float* vbe2 = (const float*)d_in[20];

    float* hin; float* agg; float* hbuf; float* vn; float* vt;
    int *deg, *off, *cur, *part, *eids;
    cudaGetSymbolAddress((void**)&hin, g_hin);
    cudaGetSymbolAddress((void**)&agg, g_agg);
    cudaGetSymbolAddress((void**)&hbuf, g_h);
    cudaGetSymbolAddress((void**)&vn, g_vn);
    cudaGetSymbolAddress((void**)&vt, g_vt);
    cudaGetSymbolAddress((void**)&deg, g_deg);
    cudaGetSymbolAddress((void**)&off, g_off);
    cudaGetSymbolAddress((void**)&cur, g_cur);
    cudaGetSymbolAddress((void**)&part, g_part);
    cudaGetSymbolAddress((void**)&eids, g_eids);

    cudaFuncSetAttribute(k_node_mlp, cudaFuncAttributeMaxDynamicSharedMemorySize,
                         MLP_SMEM_FLOATS * (int)sizeof(float));

    const float inv = 1.0f / sqrtf(1.0f + 1e-5f);

    // ---- CSR build (edge_index invariant across layers) ----
    int NB = (N + 511) / 512;           // <= 196 for N=100000
    cudaMemsetAsync(deg, 0, (size_t)N * sizeof(int));
    cudaMemsetAsync(part, 0, 256 * sizeof(int));
    k_count<<<(int)((E + 255) / 256), 256>>>(edge_index, deg, (int)E);
    k_scan1<<<NB, 512>>>(deg, off, part, N);
    k_scan2<<<1, 256>>>(part);
    k_scan3<<<NB, 512>>>(off, cur, part, N, (int)E);
    k_scatter<<<(int)((E + 255) / 256), 256>>>(edge_index, cur, eids, (int)E);

    k_init_vn<<<(NGRAPH * EMB + 255) / 256, 256>>>(vn_emb, vn);

    int nblk = (N + 63) / 64;
    int ablk = (N + 7) / 8;

    const float* h = input_feature;
    for (int l = 0; l < NLAYER; l++) {
        int doVT = (l < NLAYER - 1);
        if (doVT) cudaMemsetAsync(vt, 0, (size_t)NGRAPH * EMB * sizeof(float));

        k_hin_vt<<<nblk, dim3(32, 8)>>>(h, batch, vn, hin, vt, N, doVT);

        k_agg_csr<<<ablk, 256>>>(hin, edge_attr, edge_index, off, eids,
                                 cew + (size_t)l * EDIM * EMB, ceb + (size_t)l * EMB,
                                 agg, N);

        float* outp = (l == NLAYER - 1) ? (float*)d_out : hbuf;
        k_node_mlp<<<nblk, 256, MLP_SMEM_FLOATS * (int)sizeof(float)>>>(
            hin, agg,
            cw1 + (size_t)l * EMB * HID, cb1 + (size_t)l * HID,
            cw2 + (size_t)l * HID * EMB, cb2 + (size_t)l * EMB,
            bng + (size_t)l * EMB, bnb + (size_t)l * EMB,
            outp, N, doVT ? 1 : 0, inv);

        if (doVT) {
            k_vn_mlp<<<NGRAPH, 256>>>(vt, vn,
                                      vw1 + (size_t)l * EMB * HID, vb1 + (size_t)l * HID,
                                      vg1 + (size_t)l * HID, vbe1 + (size_t)l * HID,
                                      vw2 + (size_t)l * HID * EMB, vb2 + (size_t)l * EMB,
                                      vg2 + (size_t)l * EMB, vbe2 + (size_t)l * EMB, inv);
        }
        h = outp;
    }
}